// round 2
// baseline (speedup 1.0000x reference)
#include <cuda_runtime.h>
#include <cstdint>

#define IN_DIM   64
#define HID_DIM  256
#define OUT_DIM  128
#define TM       128     // items per CTA
#define CH       64      // hidden chunk
#define NCH      (HID_DIM / CH)
#define NTHREADS 512
#define XT_STRIDE 132    // TM + 4 pad (keeps 16B alignment, breaks bank stride)
#define HT_STRIDE 132

// shared memory layout (float offsets)
#define SXT_OFF  0                              // [IN_DIM][XT_STRIDE] x^T tile
#define SHT_OFF  (SXT_OFF + IN_DIM * XT_STRIDE) // [CH][HT_STRIDE]    relu(h)^T chunk
#define SW1_OFF  (SHT_OFF + CH * HT_STRIDE)     // [IN_DIM][CH]       W1 chunk
#define SW2_OFF  (SW1_OFF + IN_DIM * CH)        // [CH][OUT_DIM]      W2 chunk
#define SIDX_OFF (SW2_OFF + CH * OUT_DIM)       // [TM] int bins
#define SMEM_FLOATS (SIDX_OFF + TM)
#define SMEM_BYTES  (SMEM_FLOATS * 4)           // 117,760 B < 227 KB

__device__ int g_idx_is_64;

// ---- packed f32x2 helpers (sm_100+) -------------------------------------
__device__ __forceinline__ void ffma2(unsigned long long& d,
                                      unsigned long long a,
                                      unsigned long long b) {
    asm("fma.rn.f32x2 %0, %1, %2, %0;" : "+l"(d) : "l"(a), "l"(b));
}
__device__ __forceinline__ unsigned long long pack2(float v) {
    unsigned long long r;
    unsigned int u = __float_as_uint(v);
    asm("mov.b64 %0, {%1, %1};" : "=l"(r) : "r"(u));
    return r;
}
__device__ __forceinline__ float2 unpack2(unsigned long long v) {
    unsigned int lo, hi;
    asm("mov.b64 {%0, %1}, %2;" : "=r"(lo), "=r"(hi) : "l"(v));
    return make_float2(__uint_as_float(lo), __uint_as_float(hi));
}
__device__ __forceinline__ void red_add4(float* p, float a, float b, float c, float d) {
    asm volatile("red.global.add.v4.f32 [%0], {%1, %2, %3, %4};"
                 :: "l"(p), "f"(a), "f"(b), "f"(c), "f"(d) : "memory");
}

// idx dtype probe: if the buffer is int64, the high 32-bit word of every
// element is 0 (values < 4096). If it is int32, odd int32 slots are random
// indices; 64 consecutive zeros there has probability ~4096^-64 ~ 0.
__global__ void detect_idx_kernel(const int* __restrict__ idx32) {
    if (threadIdx.x == 0) {
        int ok = 1;
        #pragma unroll 1
        for (int i = 0; i < 64; ++i) ok &= (idx32[2 * i + 1] == 0);
        g_idx_is_64 = ok;
    }
}

__global__ __launch_bounds__(NTHREADS, 1)
void item_encoder_kernel(const float* __restrict__ x,
                         const int*   __restrict__ idx32,
                         const float* __restrict__ W1,
                         const float* __restrict__ b1,
                         const float* __restrict__ W2,
                         const float* __restrict__ b2,
                         float* __restrict__ out,
                         int n_items)
{
    extern __shared__ float sm[];
    float* sXT = sm + SXT_OFF;
    float* sHT = sm + SHT_OFF;
    float* sW1 = sm + SW1_OFF;
    float* sW2 = sm + SW2_OFF;
    int*   sIdx = (int*)(sm + SIDX_OFF);

    const int tid = threadIdx.x;
    const long long item0 = (long long)blockIdx.x * TM;
    const int is64 = g_idx_is_64;

    // ---- stage x tile transposed: sXT[k][row] ---------------------------
    for (int i = tid; i < TM * IN_DIM; i += NTHREADS) {
        int k   = i & (IN_DIM - 1);
        int row = i >> 6;
        long long item = item0 + row;
        float v = 0.f;
        if (item < n_items) v = x[item * IN_DIM + k];
        sXT[k * XT_STRIDE + row] = v;
    }
    if (tid < TM) {
        long long item = item0 + tid;
        int bin = -1;
        if (item < n_items)
            bin = is64 ? (int)((const long long*)idx32)[item] : idx32[item];
        sIdx[tid] = bin;
    }

    // ---- GEMM2 accumulators: rows packed in pairs (f32x2 lanes) ---------
    const int rt2 = tid >> 5, ct2 = tid & 31;
    const int row2 = rt2 * 8, col2 = ct2 * 4;
    unsigned long long oacc[4][4];   // [row-pair][col], lanes = {even,odd row}
    #pragma unroll
    for (int i = 0; i < 4; ++i) {
        unsigned long long bb = pack2(b2[col2 + i]);
        #pragma unroll
        for (int p = 0; p < 4; ++p) oacc[p][i] = bb;
    }

    const int rt1 = tid >> 4, ct1 = tid & 15;
    const int row1 = rt1 * 4, col1 = ct1 * 4;

    for (int c = 0; c < NCH; ++c) {
        __syncthreads();   // previous GEMM2 done / x staged before reload

        // ---- load weight chunks --------------------------------------
        {
            const float4* g1 = (const float4*)W1;   // row = 64 f4
            float4* s1 = (float4*)sW1;              // row = 16 f4
            #pragma unroll
            for (int p = tid; p < IN_DIM * (CH / 4); p += NTHREADS) {
                int k = p >> 4, j4 = p & 15;
                s1[k * 16 + j4] = g1[k * 64 + c * 16 + j4];
            }
            const float4* g2 = (const float4*)W2;   // row = 32 f4
            float4* s2 = (float4*)sW2;
            #pragma unroll
            for (int p = tid; p < CH * (OUT_DIM / 4); p += NTHREADS) {
                int k = p >> 5, j4 = p & 31;
                s2[k * 32 + j4] = g2[(c * CH + k) * 32 + j4];
            }
        }
        __syncthreads();

        // ---- GEMM1: Hc = relu(X @ W1c + b1c), write transposed -------
        {
            unsigned long long acc[2][4];
            #pragma unroll
            for (int i = 0; i < 4; ++i) {
                unsigned long long bb = pack2(b1[c * CH + col1 + i]);
                acc[0][i] = bb; acc[1][i] = bb;
            }
            #pragma unroll 8
            for (int k = 0; k < IN_DIM; ++k) {
                ulonglong2 a = *(const ulonglong2*)&sXT[k * XT_STRIDE + row1];
                float4 bv = *(const float4*)&sW1[k * CH + col1];
                unsigned long long p0 = pack2(bv.x), p1 = pack2(bv.y),
                                   p2 = pack2(bv.z), p3 = pack2(bv.w);
                ffma2(acc[0][0], a.x, p0); ffma2(acc[1][0], a.y, p0);
                ffma2(acc[0][1], a.x, p1); ffma2(acc[1][1], a.y, p1);
                ffma2(acc[0][2], a.x, p2); ffma2(acc[1][2], a.y, p2);
                ffma2(acc[0][3], a.x, p3); ffma2(acc[1][3], a.y, p3);
            }
            #pragma unroll
            for (int i = 0; i < 4; ++i) {
                float2 lo = unpack2(acc[0][i]);
                float2 hi = unpack2(acc[1][i]);
                float4 v = make_float4(fmaxf(lo.x, 0.f), fmaxf(lo.y, 0.f),
                                       fmaxf(hi.x, 0.f), fmaxf(hi.y, 0.f));
                *(float4*)&sHT[(col1 + i) * HT_STRIDE + row1] = v;
            }
        }
        __syncthreads();

        // ---- GEMM2: O += Hc @ W2c ------------------------------------
        #pragma unroll 8
        for (int k = 0; k < CH; ++k) {
            ulonglong2 a01 = *(const ulonglong2*)&sHT[k * HT_STRIDE + row2];
            ulonglong2 a23 = *(const ulonglong2*)&sHT[k * HT_STRIDE + row2 + 4];
            float4 bv = *(const float4*)&sW2[k * OUT_DIM + col2];
            unsigned long long p0 = pack2(bv.x), p1 = pack2(bv.y),
                               p2 = pack2(bv.z), p3 = pack2(bv.w);
            ffma2(oacc[0][0], a01.x, p0); ffma2(oacc[1][0], a01.y, p0);
            ffma2(oacc[2][0], a23.x, p0); ffma2(oacc[3][0], a23.y, p0);
            ffma2(oacc[0][1], a01.x, p1); ffma2(oacc[1][1], a01.y, p1);
            ffma2(oacc[2][1], a23.x, p1); ffma2(oacc[3][1], a23.y, p1);
            ffma2(oacc[0][2], a01.x, p2); ffma2(oacc[1][2], a01.y, p2);
            ffma2(oacc[2][2], a23.x, p2); ffma2(oacc[3][2], a23.y, p2);
            ffma2(oacc[0][3], a01.x, p3); ffma2(oacc[1][3], a01.y, p3);
            ffma2(oacc[2][3], a23.x, p3); ffma2(oacc[3][3], a23.y, p3);
        }
    }

    // ---- scatter-add epilogue: vectorized L2 reductions ----------------
    #pragma unroll
    for (int p = 0; p < 4; ++p) {
        int rowE = row2 + 2 * p;
        int binE = sIdx[rowE];
        int binO = sIdx[rowE + 1];
        float xe[4], xo[4];
        #pragma unroll
        for (int i = 0; i < 4; ++i) {
            float2 f = unpack2(oacc[p][i]);
            xe[i] = f.x; xo[i] = f.y;
        }
        if (binE >= 0)
            red_add4(out + (size_t)binE * OUT_DIM + col2, xe[0], xe[1], xe[2], xe[3]);
        if (binO >= 0)
            red_add4(out + (size_t)binO * OUT_DIM + col2, xo[0], xo[1], xo[2], xo[3]);
    }
}

extern "C" void kernel_launch(void* const* d_in, const int* in_sizes, int n_in,
                              void* d_out, int out_size)
{
    const float* x     = (const float*)d_in[0];
    const int*   idx32 = (const int*)d_in[1];

    // weights base: metadata order is x, idxs, n_bins(scalar), W1, b1, W2, b2.
    // If the scalar n_bins is not materialized as an input, W1 lands at slot 2.
    int wbase = 3;
    if (n_in >= 3 && in_sizes[2] == IN_DIM * HID_DIM) wbase = 2;
    const float* W1 = (const float*)d_in[wbase + 0];
    const float* b1 = (const float*)d_in[wbase + 1];
    const float* W2 = (const float*)d_in[wbase + 2];
    const float* b2 = (const float*)d_in[wbase + 3];
    float* out = (float*)d_out;

    const int n_items = in_sizes[0] / IN_DIM;

    cudaFuncSetAttribute(item_encoder_kernel,
                         cudaFuncAttributeMaxDynamicSharedMemorySize, SMEM_BYTES);

    cudaMemsetAsync(d_out, 0, (size_t)out_size * sizeof(float), (cudaStream_t)0);
    detect_idx_kernel<<<1, 32, 0, (cudaStream_t)0>>>(idx32);

    const int grid = (n_items + TM - 1) / TM;
    item_encoder_kernel<<<grid, NTHREADS, SMEM_BYTES, (cudaStream_t)0>>>(
        x, idx32, W1, b1, W2, b2, out, n_items);
}

// round 4
// speedup vs baseline: 2.9400x; 2.9400x over previous
#include <cuda_runtime.h>
#include <cstdint>

#define IN_DIM   64
#define HID_DIM  256
#define OUT_DIM  128
#define TM       128
#define NTH      256

#define W1_FRAGS (32 * 4 * 32)    // [nt=32][kt=4][lane=32]
#define W2_FRAGS (16 * 16 * 32)   // [nt=16][kt=16][lane=32]

__device__ uint2 gW1H[W1_FRAGS], gW1L[W1_FRAGS];
__device__ uint2 gW2H[W2_FRAGS], gW2L[W2_FRAGS];
__device__ int g_idx_is_64;

// ---- smem byte offsets --------------------------------------------------
#define SMB_W1H  0
#define SMB_W1L  32768
#define SMB_W2H  65536
#define SMB_W2L  131072
#define SMB_B1   196608
#define SMB_B2   197632
#define SMB_IDX  198144
#define SMEM_TOTAL 198656   // ~194 KB

// ---- helpers ------------------------------------------------------------
__device__ __forceinline__ uint32_t pkbf(float lo, float hi) {   // low half = lo
    uint32_t r;
    asm("cvt.rn.bf16x2.f32 %0, %1, %2;" : "=r"(r) : "f"(hi), "f"(lo));
    return r;
}
__device__ __forceinline__ float bflo(uint32_t p) { return __uint_as_float(p << 16); }
__device__ __forceinline__ float bfhi(uint32_t p) { return __uint_as_float(p & 0xffff0000u); }

__device__ __forceinline__ void mma16816(float* c, const uint32_t* a, uint2 b) {
    asm volatile(
        "mma.sync.aligned.m16n8k16.row.col.f32.bf16.bf16.f32 "
        "{%0,%1,%2,%3}, {%4,%5,%6,%7}, {%8,%9}, {%0,%1,%2,%3};"
        : "+f"(c[0]), "+f"(c[1]), "+f"(c[2]), "+f"(c[3])
        : "r"(a[0]), "r"(a[1]), "r"(a[2]), "r"(a[3]), "r"(b.x), "r"(b.y));
}
__device__ __forceinline__ void red_add2(float* p, float a, float b) {
    asm volatile("red.global.add.v2.f32 [%0], {%1, %2};"
                 :: "l"(p), "f"(a), "f"(b) : "memory");
}
__device__ __forceinline__ void split_pair(float a, float b, uint32_t& h, uint32_t& l) {
    h = pkbf(a, b);
    l = pkbf(a - bflo(h), b - bfhi(h));
}

// ---- prep: weights -> bf16 hi/lo, fragment-linear layout ----------------
__global__ void prep_weights(const float* __restrict__ W1, const float* __restrict__ W2) {
    int t = blockIdx.x * blockDim.x + threadIdx.x;
    if (t < W1_FRAGS) {
        int lane = t & 31, kt = (t >> 5) & 3, nt = t >> 7;
        int n = nt * 8 + (lane >> 2), k0 = kt * 16 + (lane & 3) * 2;
        float w00 = W1[k0 * HID_DIM + n],       w01 = W1[(k0 + 1) * HID_DIM + n];
        float w10 = W1[(k0 + 8) * HID_DIM + n], w11 = W1[(k0 + 9) * HID_DIM + n];
        uint32_t h0, l0, h1, l1;
        split_pair(w00, w01, h0, l0);
        split_pair(w10, w11, h1, l1);
        gW1H[t] = make_uint2(h0, h1);
        gW1L[t] = make_uint2(l0, l1);
    } else if (t < W1_FRAGS + W2_FRAGS) {
        int t2 = t - W1_FRAGS;
        int lane = t2 & 31, kt = (t2 >> 5) & 15, nt = t2 >> 9;
        int n = nt * 8 + (lane >> 2), k0 = kt * 16 + (lane & 3) * 2;
        float w00 = W2[k0 * OUT_DIM + n],       w01 = W2[(k0 + 1) * OUT_DIM + n];
        float w10 = W2[(k0 + 8) * OUT_DIM + n], w11 = W2[(k0 + 9) * OUT_DIM + n];
        uint32_t h0, l0, h1, l1;
        split_pair(w00, w01, h0, l0);
        split_pair(w10, w11, h1, l1);
        gW2H[t2] = make_uint2(h0, h1);
        gW2L[t2] = make_uint2(l0, l1);
    }
}

__global__ void detect_idx_kernel(const int* __restrict__ idx32) {
    if (threadIdx.x == 0) {
        int ok = 1;
        #pragma unroll 1
        for (int i = 0; i < 64; ++i) ok &= (idx32[2 * i + 1] == 0);
        g_idx_is_64 = ok;
    }
}

// ---- main fused kernel --------------------------------------------------
__global__ __launch_bounds__(NTH, 1)
void item_encoder_mma(const float* __restrict__ x,
                      const int*   __restrict__ idx32,
                      const float* __restrict__ b1,
                      const float* __restrict__ b2,
                      float* __restrict__ out,
                      int n_items)
{
    extern __shared__ char smc[];
    const uint2* sW1H = (const uint2*)(smc + SMB_W1H);
    const uint2* sW1L = (const uint2*)(smc + SMB_W1L);
    const uint2* sW2H = (const uint2*)(smc + SMB_W2H);
    const uint2* sW2L = (const uint2*)(smc + SMB_W2L);
    float* b1s = (float*)(smc + SMB_B1);
    float* b2s = (float*)(smc + SMB_B2);
    int*   sIdx = (int*)(smc + SMB_IDX);

    const int tid = threadIdx.x;
    const int wid = tid >> 5, lane = tid & 31;
    const int gid = lane >> 2, tig = lane & 3;
    const long long item0 = (long long)blockIdx.x * TM;

    // ---- stage weights (raw uint4 copy) + biases + bins -----------------
    {
        uint4* d = (uint4*)smc;
        const uint4* s1h = (const uint4*)gW1H;
        const uint4* s1l = (const uint4*)gW1L;
        const uint4* s2h = (const uint4*)gW2H;
        const uint4* s2l = (const uint4*)gW2L;
        #pragma unroll 4
        for (int i = tid; i < 2048; i += NTH) {
            d[i]        = s1h[i];
            d[i + 2048] = s1l[i];
        }
        #pragma unroll 4
        for (int i = tid; i < 4096; i += NTH) {
            d[i + 4096] = s2h[i];
            d[i + 8192] = s2l[i];
        }
        b1s[tid] = b1[tid];
        if (tid < TM) {
            b2s[tid] = b2[tid];
            long long gi = item0 + tid;
            int bin = -1;
            if (gi < n_items)
                bin = g_idx_is_64 ? (int)((const long long*)idx32)[gi]
                                  : idx32[gi];
            sIdx[tid] = bin;
        }
    }
    __syncthreads();

    // ---- x A-fragments straight from gmem (hi/lo split) -----------------
    long long r0 = item0 + wid * 16 + gid;
    long long r1 = r0 + 8;
    uint32_t xh[4][4], xl[4][4];
    {
        const float* p0 = x + r0 * IN_DIM + tig * 2;
        const float* p1 = x + r1 * IN_DIM + tig * 2;
        #pragma unroll
        for (int kt = 0; kt < 4; ++kt) {
            float2 f0 = make_float2(0.f, 0.f), f1 = f0, f2 = f0, f3 = f0;
            if (r0 < n_items) { f0 = *(const float2*)(p0 + kt * 16);
                                f2 = *(const float2*)(p0 + kt * 16 + 8); }
            if (r1 < n_items) { f1 = *(const float2*)(p1 + kt * 16);
                                f3 = *(const float2*)(p1 + kt * 16 + 8); }
            split_pair(f0.x, f0.y, xh[kt][0], xl[kt][0]);
            split_pair(f1.x, f1.y, xh[kt][1], xl[kt][1]);
            split_pair(f2.x, f2.y, xh[kt][2], xl[kt][2]);
            split_pair(f3.x, f3.y, xh[kt][3], xl[kt][3]);
        }
    }

    float o[16][4];
    #pragma unroll
    for (int nt = 0; nt < 16; ++nt)
        #pragma unroll
        for (int q = 0; q < 4; ++q) o[nt][q] = 0.f;

    // ---- 4 hidden chunks of 64 ------------------------------------------
    #pragma unroll 1
    for (int c = 0; c < 4; ++c) {
        // GEMM1: C1[16 rows x 64 cols] = x @ W1[:, chunk]
        float c1[8][4];
        #pragma unroll
        for (int j = 0; j < 8; ++j)
            #pragma unroll
            for (int q = 0; q < 4; ++q) c1[j][q] = 0.f;

        #pragma unroll
        for (int j = 0; j < 8; ++j) {
            int fb = ((c * 8 + j) * 4) * 32 + lane;
            #pragma unroll
            for (int kt = 0; kt < 4; ++kt) {
                uint2 bh = sW1H[fb + kt * 32];
                uint2 bl = sW1L[fb + kt * 32];
                mma16816(c1[j], xh[kt], bh);
                mma16816(c1[j], xh[kt], bl);
                mma16816(c1[j], xl[kt], bh);
            }
        }

        // bias + relu + hi/lo re-split: C-fragments -> A-fragments (in regs)
        uint32_t ah[4][4], al[4][4];
        #pragma unroll
        for (int j = 0; j < 8; ++j) {
            float2 bb = *(const float2*)&b1s[c * 64 + j * 8 + tig * 2];
            float v0 = fmaxf(c1[j][0] + bb.x, 0.f);
            float v1 = fmaxf(c1[j][1] + bb.y, 0.f);
            float v2 = fmaxf(c1[j][2] + bb.x, 0.f);
            float v3 = fmaxf(c1[j][3] + bb.y, 0.f);
            uint32_t p0, q0, p1, q1;
            split_pair(v0, v1, p0, q0);
            split_pair(v2, v3, p1, q1);
            int kt = j >> 1, s = (j & 1) * 2;
            ah[kt][s] = p0; ah[kt][s + 1] = p1;
            al[kt][s] = q0; al[kt][s + 1] = q1;
        }

        // GEMM2: O += H[:, chunk] @ W2[chunk, :]
        #pragma unroll
        for (int nt = 0; nt < 16; ++nt) {
            int fb = (nt * 16 + c * 4) * 32 + lane;
            #pragma unroll
            for (int kt = 0; kt < 4; ++kt) {
                uint2 bh = sW2H[fb + kt * 32];
                uint2 bl = sW2L[fb + kt * 32];
                mma16816(o[nt], ah[kt], bh);
                mma16816(o[nt], ah[kt], bl);
                mma16816(o[nt], al[kt], bh);
            }
        }
    }

    // ---- epilogue: +b2, scatter-add ------------------------------------
    int lr0 = wid * 16 + gid;
    int bin0 = sIdx[lr0];
    int bin1 = sIdx[lr0 + 8];
    #pragma unroll
    for (int nt = 0; nt < 16; ++nt) {
        int col = nt * 8 + tig * 2;
        float2 bb = *(const float2*)&b2s[col];
        if (bin0 >= 0)
            red_add2(out + (size_t)bin0 * OUT_DIM + col, o[nt][0] + bb.x, o[nt][1] + bb.y);
        if (bin1 >= 0)
            red_add2(out + (size_t)bin1 * OUT_DIM + col, o[nt][2] + bb.x, o[nt][3] + bb.y);
    }
}

extern "C" void kernel_launch(void* const* d_in, const int* in_sizes, int n_in,
                              void* d_out, int out_size)
{
    const float* x     = (const float*)d_in[0];
    const int*   idx32 = (const int*)d_in[1];
    int wbase = 3;
    if (n_in >= 3 && in_sizes[2] == IN_DIM * HID_DIM) wbase = 2;
    const float* W1 = (const float*)d_in[wbase + 0];
    const float* b1 = (const float*)d_in[wbase + 1];
    const float* W2 = (const float*)d_in[wbase + 2];
    const float* b2 = (const float*)d_in[wbase + 3];
    float* out = (float*)d_out;

    const int n_items = in_sizes[0] / IN_DIM;

    cudaFuncSetAttribute(item_encoder_mma,
                         cudaFuncAttributeMaxDynamicSharedMemorySize, SMEM_TOTAL);

    cudaMemsetAsync(d_out, 0, (size_t)out_size * sizeof(float), (cudaStream_t)0);
    detect_idx_kernel<<<1, 32, 0, (cudaStream_t)0>>>(idx32);
    prep_weights<<<(W1_FRAGS + W2_FRAGS) / NTH, NTH, 0, (cudaStream_t)0>>>(W1, W2);

    const int grid = (n_items + TM - 1) / TM;
    item_encoder_mma<<<grid, NTH, SMEM_TOTAL, (cudaStream_t)0>>>(
        x, idx32, b1, b2, out, n_items);
}

// round 6
// speedup vs baseline: 3.9905x; 1.3573x over previous
#include <cuda_runtime.h>
#include <cstdint>

#define IN_DIM   64
#define HID_DIM  256
#define OUT_DIM  128
#define TM       128
#define NTH      256
#define NSM      148

#define W1_FRAGS (32 * 4 * 32)    // [nt=32][kt=4][lane=32]
#define W2_FRAGS (16 * 16 * 32)   // [nt=16][kt=16][lane=32]

__device__ uint2 gW1H[W1_FRAGS], gW1L[W1_FRAGS];
__device__ uint2 gW2H[W2_FRAGS], gW2L[W2_FRAGS];
__device__ int g_idx_is_64;

// ---- smem byte offsets --------------------------------------------------
#define SMB_W1H  0
#define SMB_W1L  32768
#define SMB_W2H  65536
#define SMB_W2L  131072
#define SMB_B1   196608
#define SMB_B2   197632
#define SMEM_TOTAL 198656   // ~194 KB

// ---- helpers ------------------------------------------------------------
__device__ __forceinline__ uint32_t pkbf(float lo, float hi) {   // low half = lo
    uint32_t r;
    asm("cvt.rn.bf16x2.f32 %0, %1, %2;" : "=r"(r) : "f"(hi), "f"(lo));
    return r;
}
__device__ __forceinline__ float bflo(uint32_t p) { return __uint_as_float(p << 16); }
__device__ __forceinline__ float bfhi(uint32_t p) { return __uint_as_float(p & 0xffff0000u); }

__device__ __forceinline__ void mma16816(float* c, const uint32_t* a, uint2 b) {
    asm volatile(
        "mma.sync.aligned.m16n8k16.row.col.f32.bf16.bf16.f32 "
        "{%0,%1,%2,%3}, {%4,%5,%6,%7}, {%8,%9}, {%0,%1,%2,%3};"
        : "+f"(c[0]), "+f"(c[1]), "+f"(c[2]), "+f"(c[3])
        : "r"(a[0]), "r"(a[1]), "r"(a[2]), "r"(a[3]), "r"(b.x), "r"(b.y));
}
__device__ __forceinline__ void red_add2(float* p, float a, float b) {
    asm volatile("red.global.add.v2.f32 [%0], {%1, %2};"
                 :: "l"(p), "f"(a), "f"(b) : "memory");
}
__device__ __forceinline__ void prefetch_l2(const void* p) {
    asm volatile("prefetch.global.L2 [%0];" :: "l"(p));
}
__device__ __forceinline__ void split_pair(float a, float b, uint32_t& h, uint32_t& l) {
    h = pkbf(a, b);
    l = pkbf(a - bflo(h), b - bfhi(h));
}

// ---- prep: weights -> bf16 hi/lo, fragment-linear layout ----------------
__global__ void prep_weights(const float* __restrict__ W1, const float* __restrict__ W2) {
    int t = blockIdx.x * blockDim.x + threadIdx.x;
    if (t < W1_FRAGS) {
        int lane = t & 31, kt = (t >> 5) & 3, nt = t >> 7;
        int n = nt * 8 + (lane >> 2), k0 = kt * 16 + (lane & 3) * 2;
        float w00 = W1[k0 * HID_DIM + n],       w01 = W1[(k0 + 1) * HID_DIM + n];
        float w10 = W1[(k0 + 8) * HID_DIM + n], w11 = W1[(k0 + 9) * HID_DIM + n];
        uint32_t h0, l0, h1, l1;
        split_pair(w00, w01, h0, l0);
        split_pair(w10, w11, h1, l1);
        gW1H[t] = make_uint2(h0, h1);
        gW1L[t] = make_uint2(l0, l1);
    } else if (t < W1_FRAGS + W2_FRAGS) {
        int t2 = t - W1_FRAGS;
        int lane = t2 & 31, kt = (t2 >> 5) & 15, nt = t2 >> 9;
        int n = nt * 8 + (lane >> 2), k0 = kt * 16 + (lane & 3) * 2;
        float w00 = W2[k0 * OUT_DIM + n],       w01 = W2[(k0 + 1) * OUT_DIM + n];
        float w10 = W2[(k0 + 8) * OUT_DIM + n], w11 = W2[(k0 + 9) * OUT_DIM + n];
        uint32_t h0, l0, h1, l1;
        split_pair(w00, w01, h0, l0);
        split_pair(w10, w11, h1, l1);
        gW2H[t2] = make_uint2(h0, h1);
        gW2L[t2] = make_uint2(l0, l1);
    }
}

// parallel idx dtype probe: 32 odd words, all-zero <=> int64 (values < 4096)
__global__ void detect_idx_kernel(const int* __restrict__ idx32) {
    int ok = (idx32[2 * threadIdx.x + 1] == 0);
    unsigned m = __ballot_sync(0xffffffffu, ok);
    if (threadIdx.x == 0) g_idx_is_64 = (m == 0xffffffffu);
}

// ---- main persistent fused kernel ---------------------------------------
__global__ __launch_bounds__(NTH, 1)
void item_encoder_mma(const float* __restrict__ x,
                      const int*   __restrict__ idx32,
                      const float* __restrict__ b1,
                      const float* __restrict__ b2,
                      float* __restrict__ out,
                      int n_items, int n_tiles)
{
    extern __shared__ char smc[];
    const uint2* sW1H = (const uint2*)(smc + SMB_W1H);
    const uint2* sW1L = (const uint2*)(smc + SMB_W1L);
    const uint2* sW2H = (const uint2*)(smc + SMB_W2H);
    const uint2* sW2L = (const uint2*)(smc + SMB_W2L);
    float* b1s = (float*)(smc + SMB_B1);
    float* b2s = (float*)(smc + SMB_B2);

    const int tid = threadIdx.x;
    const int wid = tid >> 5, lane = tid & 31;
    const int gid = lane >> 2, tig = lane & 3;

    // ---- one-time prologue: stage weights + biases ----------------------
    {
        uint4* d = (uint4*)smc;
        const uint4* s1h = (const uint4*)gW1H;
        const uint4* s1l = (const uint4*)gW1L;
        const uint4* s2h = (const uint4*)gW2H;
        const uint4* s2l = (const uint4*)gW2L;
        #pragma unroll 4
        for (int i = tid; i < 2048; i += NTH) {
            d[i]        = s1h[i];
            d[i + 2048] = s1l[i];
        }
        #pragma unroll 4
        for (int i = tid; i < 4096; i += NTH) {
            d[i + 4096] = s2h[i];
            d[i + 8192] = s2l[i];
        }
        b1s[tid] = b1[tid];
        if (tid < TM) b2s[tid] = b2[tid];
    }
    __syncthreads();
    const int is64 = g_idx_is_64;
    const long long stride_items = (long long)gridDim.x * TM;

    // ---- persistent tile loop (no syncs inside) -------------------------
    for (int tile = blockIdx.x; tile < n_tiles; tile += gridDim.x) {
        const long long item0 = (long long)tile * TM;

        // L2 prefetch of next tile's x (one 128B line per thread)
        {
            long long pfi = item0 + stride_items + (tid >> 1);
            if (pfi < n_items)
                prefetch_l2((const char*)(x + pfi * IN_DIM) + (tid & 1) * 128);
        }

        // ---- x A-fragments straight from gmem (hi/lo split) -------------
        const long long r0 = item0 + wid * 16 + gid;
        const long long r1 = r0 + 8;
        uint32_t xh[4][4], xl[4][4];
        {
            const float* p0 = x + r0 * IN_DIM + tig * 2;
            const float* p1 = x + r1 * IN_DIM + tig * 2;
            #pragma unroll
            for (int kt = 0; kt < 4; ++kt) {
                float2 f0 = make_float2(0.f, 0.f), f1 = f0, f2 = f0, f3 = f0;
                if (r0 < n_items) { f0 = *(const float2*)(p0 + kt * 16);
                                    f2 = *(const float2*)(p0 + kt * 16 + 8); }
                if (r1 < n_items) { f1 = *(const float2*)(p1 + kt * 16);
                                    f3 = *(const float2*)(p1 + kt * 16 + 8); }
                split_pair(f0.x, f0.y, xh[kt][0], xl[kt][0]);
                split_pair(f1.x, f1.y, xh[kt][1], xl[kt][1]);
                split_pair(f2.x, f2.y, xh[kt][2], xl[kt][2]);
                split_pair(f3.x, f3.y, xh[kt][3], xl[kt][3]);
            }
        }
        // bins for this thread's two rows (direct gmem, no smem)
        int bin0 = -1, bin1 = -1;
        if (r0 < n_items)
            bin0 = is64 ? (int)((const long long*)idx32)[r0] : idx32[r0];
        if (r1 < n_items)
            bin1 = is64 ? (int)((const long long*)idx32)[r1] : idx32[r1];

        float o[16][4];
        #pragma unroll
        for (int nt = 0; nt < 16; ++nt)
            #pragma unroll
            for (int q = 0; q < 4; ++q) o[nt][q] = 0.f;

        // ---- 4 hidden chunks of 64 --------------------------------------
        #pragma unroll 1
        for (int c = 0; c < 4; ++c) {
            float c1[8][4];
            #pragma unroll
            for (int j = 0; j < 8; ++j)
                #pragma unroll
                for (int q = 0; q < 4; ++q) c1[j][q] = 0.f;

            #pragma unroll
            for (int j = 0; j < 8; ++j) {
                int fb = ((c * 8 + j) * 4) * 32 + lane;
                #pragma unroll
                for (int kt = 0; kt < 4; ++kt) {
                    uint2 bh = sW1H[fb + kt * 32];
                    uint2 bl = sW1L[fb + kt * 32];
                    mma16816(c1[j], xh[kt], bh);
                    mma16816(c1[j], xh[kt], bl);
                    mma16816(c1[j], xl[kt], bh);
                }
            }

            // bias + relu + hi/lo re-split: C-fragments -> A-fragments
            uint32_t ah[4][4], al[4][4];
            #pragma unroll
            for (int j = 0; j < 8; ++j) {
                float2 bb = *(const float2*)&b1s[c * 64 + j * 8 + tig * 2];
                float v0 = fmaxf(c1[j][0] + bb.x, 0.f);
                float v1 = fmaxf(c1[j][1] + bb.y, 0.f);
                float v2 = fmaxf(c1[j][2] + bb.x, 0.f);
                float v3 = fmaxf(c1[j][3] + bb.y, 0.f);
                uint32_t p0, q0, p1, q1;
                split_pair(v0, v1, p0, q0);
                split_pair(v2, v3, p1, q1);
                int kt = j >> 1, s = (j & 1) * 2;
                ah[kt][s] = p0; ah[kt][s + 1] = p1;
                al[kt][s] = q0; al[kt][s + 1] = q1;
            }

            // GEMM2: O += H[:, chunk] @ W2[chunk, :]
            #pragma unroll
            for (int nt = 0; nt < 16; ++nt) {
                int fb = (nt * 16 + c * 4) * 32 + lane;
                #pragma unroll
                for (int kt = 0; kt < 4; ++kt) {
                    uint2 bh = sW2H[fb + kt * 32];
                    uint2 bl = sW2L[fb + kt * 32];
                    mma16816(o[nt], ah[kt], bh);
                    mma16816(o[nt], ah[kt], bl);
                    mma16816(o[nt], al[kt], bh);
                }
            }
        }

        // ---- epilogue: +b2, scatter-add ---------------------------------
        #pragma unroll
        for (int nt = 0; nt < 16; ++nt) {
            int col = nt * 8 + tig * 2;
            float2 bb = *(const float2*)&b2s[col];
            if (bin0 >= 0)
                red_add2(out + (size_t)bin0 * OUT_DIM + col,
                         o[nt][0] + bb.x, o[nt][1] + bb.y);
            if (bin1 >= 0)
                red_add2(out + (size_t)bin1 * OUT_DIM + col,
                         o[nt][2] + bb.x, o[nt][3] + bb.y);
        }
    }
}

extern "C" void kernel_launch(void* const* d_in, const int* in_sizes, int n_in,
                              void* d_out, int out_size)
{
    const float* x     = (const float*)d_in[0];
    const int*   idx32 = (const int*)d_in[1];
    int wbase = 3;
    if (n_in >= 3 && in_sizes[2] == IN_DIM * HID_DIM) wbase = 2;
    const float* W1 = (const float*)d_in[wbase + 0];
    const float* b1 = (const float*)d_in[wbase + 1];
    const float* W2 = (const float*)d_in[wbase + 2];
    const float* b2 = (const float*)d_in[wbase + 3];
    float* out = (float*)d_out;

    const int n_items = in_sizes[0] / IN_DIM;
    const int n_tiles = (n_items + TM - 1) / TM;

    cudaFuncSetAttribute(item_encoder_mma,
                         cudaFuncAttributeMaxDynamicSharedMemorySize, SMEM_TOTAL);

    cudaMemsetAsync(d_out, 0, (size_t)out_size * sizeof(float), (cudaStream_t)0);
    detect_idx_kernel<<<1, 32, 0, (cudaStream_t)0>>>(idx32);
    prep_weights<<<(W1_FRAGS + W2_FRAGS) / NTH, NTH, 0, (cudaStream_t)0>>>(W1, W2);

    item_encoder_mma<<<NSM, NTH, SMEM_TOTAL, (cudaStream_t)0>>>(
        x, idx32, b1, b2, out, n_items, n_tiles);
}